// round 16
// baseline (speedup 1.0000x reference)
#include <cuda_runtime.h>
#include <cuda_bf16.h>
#include <cuda_fp16.h>
#include <cstdint>

// Problem constants
#define NB   4
#define SEQ  2048
#define EMB  1024
#define NH   16
#define HD   64
#define MROWS (NB*SEQ)   // 8192

// ---------------------------------------------------------------------------
// Scratch (static device arrays) — all-fp16 pipeline
// ---------------------------------------------------------------------------
__device__ __half g_Xh[MROWS*EMB];          // input fp16
__device__ __half g_Ct[MROWS*EMB];          // ctx fp16 [n,l,e]
__device__ __half g_Qs[MROWS*EMB];          // [n,h,l,d], scaled by log2e/8
__device__ __half g_Kf[MROWS*EMB];          // [n,h,l,d]
__device__ __half g_Vt[MROWS*EMB];          // [n,h,d,l]
__device__ __half g_Wt[4*(size_t)EMB*EMB];  // transposed [n][k] x4 (q,k,v,p)
__device__ float g_y[MROWS*EMB];

// ---------------------------------------------------------------------------
// PTX helpers (arch-neutral sm_80-era instructions)
// ---------------------------------------------------------------------------
__device__ __forceinline__ uint32_t s2u(const void* p) {
    return (uint32_t)__cvta_generic_to_shared(p);
}
#define CP16(d, s) asm volatile("cp.async.cg.shared.global [%0], [%1], 16;" :: "r"(d), "l"(s))
#define CPCOMMIT() asm volatile("cp.async.commit_group;")
#define CPWAIT0()  asm volatile("cp.async.wait_group 0;")
#define CPWAIT1()  asm volatile("cp.async.wait_group 1;")
#define LDSM4(r0,r1,r2,r3,a) \
    asm volatile("ldmatrix.sync.aligned.m8n8.x4.shared.b16 {%0,%1,%2,%3}, [%4];" \
        : "=r"(r0),"=r"(r1),"=r"(r2),"=r"(r3) : "r"(a))

__device__ __forceinline__ void mma16816h(float* c, const uint32_t* a, const uint32_t* b) {
    asm volatile(
        "mma.sync.aligned.m16n8k16.row.col.f32.f16.f16.f32 "
        "{%0,%1,%2,%3}, {%4,%5,%6,%7}, {%8,%9}, {%0,%1,%2,%3};"
        : "+f"(c[0]), "+f"(c[1]), "+f"(c[2]), "+f"(c[3])
        : "r"(a[0]), "r"(a[1]), "r"(a[2]), "r"(a[3]), "r"(b[0]), "r"(b[1]));
}

__device__ __forceinline__ uint32_t h2u(__half2 h) {
    return *reinterpret_cast<uint32_t*>(&h);
}

// pack two fp32 to half2 then exp2 both (one MUFU f16x2 op)
__device__ __forceinline__ uint32_t exp2_h2(float a, float b) {
    uint32_t s = h2u(__floats2half2_rn(a, b));
    uint32_t d;
    asm("ex2.approx.f16x2 %0, %1;" : "=r"(d) : "r"(s));
    return d;
}

// ---------------------------------------------------------------------------
// Single-fp16 GEMM mainloop (R13 structure): CTA 128x128, 128 threads
// (4 warps, 2m x 2n), warp tile 64x64, double-buffered cp.async with
// compile-time (i&1) buffer selection. __launch_bounds__(128,3) caps regs
// at 170 so 3 CTAs/SM co-reside (12 warps/SM of latency hiding).
// ---------------------------------------------------------------------------
#define GBUF 36864
#define GEMM_SMEM (2*GBUF)   // 73728; epilogue Ds (128*132*4=67584) aliases 0

__device__ __forceinline__ void gemm_core(
    char* sm,
    const __half* __restrict__ A, const __half* __restrict__ B,
    int m0, int n0, float acc[4][8][4])
{
    const int tid = threadIdx.x, lane = tid & 31, w = tid >> 5;  // 4 warps
    const int wm = w >> 1, wn = w & 1;

    auto issue = [&](int chunk) {
        int kk = chunk * 64;
        uint32_t base = s2u(sm + (chunk & 1) * GBUF);
        #pragma unroll
        for (int j = 0; j < 8; j++) {
            int idx = tid + j * 128, row = idx >> 3, c = (idx & 7) * 8;
            uint32_t so = row * 144 + c * 2;
            CP16(base + so,         A + (size_t)(m0 + row) * EMB + kk + c);
            CP16(base + 18432 + so, B + (size_t)(n0 + row) * EMB + kk + c);
        }
        CPCOMMIT();
    };

    issue(0); issue(1);

    const int laR = lane & 15, laK = (lane >> 4) * 16;
    const int lbR = (lane & 7) + ((lane >> 4) & 1) * 8, lbK = ((lane >> 3) & 1) * 16;

    for (int i = 0; i < 16; i++) {
        if (i >= 14) { CPWAIT0(); } else { CPWAIT1(); }
        __syncthreads();
        uint32_t b0 = s2u(sm + (i & 1) * GBUF);
        uint32_t aS = b0, bS = b0 + 18432;
        #pragma unroll
        for (int ks = 0; ks < 4; ks++) {
            uint32_t a[4][4], b[8][2];
            #pragma unroll
            for (int ma = 0; ma < 4; ma++)
                LDSM4(a[ma][0], a[ma][1], a[ma][2], a[ma][3],
                      aS + (uint32_t)(wm * 64 + ma * 16 + laR) * 144 + ks * 32 + laK);
            #pragma unroll
            for (int nb = 0; nb < 4; nb++)
                LDSM4(b[nb*2][0], b[nb*2][1], b[nb*2+1][0], b[nb*2+1][1],
                      bS + (uint32_t)(wn * 64 + nb * 16 + lbR) * 144 + ks * 32 + lbK);
            #pragma unroll
            for (int ma = 0; ma < 4; ma++)
                #pragma unroll
                for (int na = 0; na < 8; na++)
                    mma16816h(acc[ma][na], a[ma], b[na]);
        }
        __syncthreads();
        if (i + 2 < 16) issue(i + 2);
    }
}

__device__ __forceinline__ void stage_acc(char* sm, float acc[4][8][4])
{
    float* Ds = (float*)sm;
    const int lane = threadIdx.x & 31, w = threadIdx.x >> 5;
    const int wm = w >> 1, wn = w & 1;
    const int gid = lane >> 2, qid = lane & 3;
    #pragma unroll
    for (int ma = 0; ma < 4; ma++)
        #pragma unroll
        for (int na = 0; na < 8; na++) {
            int m = wm * 64 + ma * 16 + gid, n = wn * 64 + na * 8 + qid * 2;
            float* c = acc[ma][na];
            *(float2*)&Ds[m * 132 + n]       = make_float2(c[0], c[1]);
            *(float2*)&Ds[(m + 8) * 132 + n] = make_float2(c[2], c[3]);
        }
    __syncthreads();
}

// ---------------------------------------------------------------------------
// Fused QKV projection: blockIdx.z = 0(Q) / 1(K) / 2(V). 128 threads.
// ---------------------------------------------------------------------------
__global__ __launch_bounds__(128, 3) void mma_gemm_qkv(
    const float* __restrict__ bq, const float* __restrict__ bk,
    const float* __restrict__ bv)
{
    extern __shared__ char sm[];
    const int tid = threadIdx.x, lane = tid & 31, w = tid >> 5;
    const int m0 = blockIdx.y * 128, n0 = blockIdx.x * 128;
    const int mode = blockIdx.z;
    const float* bias = (mode == 0) ? bq : (mode == 1) ? bk : bv;

    float acc[4][8][4];
    #pragma unroll
    for (int i = 0; i < 4; i++)
        #pragma unroll
        for (int j = 0; j < 8; j++)
            #pragma unroll
            for (int k = 0; k < 4; k++) acc[i][j][k] = 0.f;

    gemm_core(sm, g_Xh, g_Wt + (size_t)mode * EMB * EMB, m0, n0, acc);
    stage_acc(sm, acc);
    float* Ds = (float*)sm;

    if (mode <= 1) {
        __half* O = (mode == 0) ? g_Qs : g_Kf;
        const float scale = (mode == 0) ? 0.125f * 1.44269504089f : 1.0f;
        #pragma unroll
        for (int it = 0; it < 32; it++) {
            int t = tid + it * 128, row = t >> 5, g = t & 31;
            int c = n0 + g * 4, r = m0 + row;
            float4 v  = *(float4*)&Ds[row * 132 + g * 4];
            float4 bi = *(const float4*)&bias[c];
            v.x = (v.x + bi.x) * scale; v.y = (v.y + bi.y) * scale;
            v.z = (v.z + bi.z) * scale; v.w = (v.w + bi.w) * scale;
            int nn = r >> 11, l = r & 2047, hh = c >> 6, dd = c & 63;
            size_t o = (((size_t)(nn * NH + hh) * SEQ) + l) * HD + dd;
            *(__half2*)&O[o]     = __floats2half2_rn(v.x, v.y);
            *(__half2*)&O[o + 2] = __floats2half2_rn(v.z, v.w);
        }
    } else {
        // V transposed -> [n,h,d,l], fp16
        const int nn = m0 >> 11, lb = m0 & 2047;
        #pragma unroll
        for (int cc = 0; cc < 32; cc++) {
            int c = n0 + w * 32 + cc;
            float bi = bias[c];
            int hh = c >> 6, dd = c & 63;
            size_t ob = ((size_t)(nn * NH + hh) * HD + dd) * SEQ + lb;
            #pragma unroll
            for (int mi = 0; mi < 4; mi++) {
                int m = mi * 32 + lane;
                g_Vt[ob + m] = __float2half(Ds[m * 132 + (c - n0)] + bi);
            }
        }
    }
}

// ---------------------------------------------------------------------------
// Output projection: ctx(fp16) @ Wp + bp + residual -> g_y (fp32). 128 threads.
// ---------------------------------------------------------------------------
__global__ __launch_bounds__(128, 3) void mma_gemm_proj(
    const float* __restrict__ resid, const float* __restrict__ bias)
{
    extern __shared__ char sm[];
    const int tid = threadIdx.x;
    const int m0 = blockIdx.y * 128, n0 = blockIdx.x * 128;

    float acc[4][8][4];
    #pragma unroll
    for (int i = 0; i < 4; i++)
        #pragma unroll
        for (int j = 0; j < 8; j++)
            #pragma unroll
            for (int k = 0; k < 4; k++) acc[i][j][k] = 0.f;

    gemm_core(sm, g_Ct, g_Wt + 3 * (size_t)EMB * EMB, m0, n0, acc);
    stage_acc(sm, acc);
    float* Ds = (float*)sm;

    #pragma unroll
    for (int it = 0; it < 32; it++) {
        int t = tid + it * 128, row = t >> 5, g = t & 31;
        int c = n0 + g * 4, r = m0 + row;
        float4 v  = *(float4*)&Ds[row * 132 + g * 4];
        float4 bi = *(const float4*)&bias[c];
        float4 rv = *(const float4*)&resid[(size_t)r * EMB + c];
        v.x += bi.x + rv.x; v.y += bi.y + rv.y;
        v.z += bi.z + rv.z; v.w += bi.w + rv.w;
        *(float4*)&g_y[(size_t)r * EMB + c] = v;
    }
}

// ---------------------------------------------------------------------------
// Flash attention (unchanged R13): 128 threads, 4 warps x 32 query rows,
// shared K/V fragments, max-free softmax, ex2.approx.f16x2, ones-MMA sums.
// smem: 2 x [K (64x144=9216) | V (9216)] = 36864 B.
// ---------------------------------------------------------------------------
#define ATN_B0  0
#define ATN_B1  18432
#define ATTN_SMEM 36864

__global__ __launch_bounds__(128) void mma_attn()
{
    extern __shared__ char sm[];
    const int tid = threadIdx.x, lane = tid & 31, w = tid >> 5;  // 4 warps
    const int gid = lane >> 2, qid = lane & 3;
    const int bh = blockIdx.x, q0 = blockIdx.y * 128;

    const __half* Qp = g_Qs + ((size_t)bh * SEQ + q0) * HD;
    const __half* Kp = g_Kf + (size_t)bh * SEQ * HD;
    const __half* Vp = g_Vt + (size_t)bh * HD * SEQ;

    const int laR = lane & 15, laK = (lane >> 4) * 16;
    const int lbR = (lane & 7) + ((lane >> 4) & 1) * 8, lbK = ((lane >> 3) & 1) * 16;

    // ---- pre-loop: stage Q (128x144) into B1 area ----
    {
        uint32_t st = s2u(sm + ATN_B1);
        #pragma unroll
        for (int j = 0; j < 8; j++) {
            int idx = tid + j * 128, row = idx >> 3, c = (idx & 7) * 8;
            CP16(st + row * 144 + c * 2, Qp + (size_t)row * HD + c);
        }
        CPCOMMIT();
    }

    auto issueKV = [&](int t) {
        uint32_t base = s2u(sm + ((t & 1) ? ATN_B1 : ATN_B0));
        #pragma unroll
        for (int j = 0; j < 8; j++) {
            int idx = tid + j * 128;
            int which = idx >> 9, rem = idx & 511, row = rem >> 3, c = (rem & 7) * 8;
            uint32_t dst = base + which * 9216 + row * 144 + c * 2;
            if (which == 0) CP16(dst, Kp + (size_t)(t * 64 + row) * HD + c);
            else            CP16(dst, Vp + (size_t)row * SEQ + t * 64 + c);
        }
        CPCOMMIT();
    };

    issueKV(0);
    CPWAIT1();          // Q staging done (KV(0) may still be pending)
    __syncthreads();

    // extract Q fragments for both 16-row m-blocks (registers, all 32 tiles)
    uint32_t qf[2][4][4];
    {
        uint32_t st = s2u(sm + ATN_B1);
        #pragma unroll
        for (int mb = 0; mb < 2; mb++)
            #pragma unroll
            for (int ks = 0; ks < 4; ks++)
                LDSM4(qf[mb][ks][0], qf[mb][ks][1], qf[mb][ks][2], qf[mb][ks][3],
                      st + (uint32_t)(w * 32 + mb * 16 + laR) * 144 + ks * 32 + laK);
    }
    __syncthreads();    // B1 free for KV(1)

    float oacc[2][8][4];
    #pragma unroll
    for (int mb = 0; mb < 2; mb++)
        #pragma unroll
        for (int i = 0; i < 8; i++)
            #pragma unroll
            for (int k = 0; k < 4; k++) oacc[mb][i][k] = 0.f;
    float lacc[2][4] = {{0.f,0.f,0.f,0.f},{0.f,0.f,0.f,0.f}};
    const uint32_t ones2[2] = {0x3C003C00u, 0x3C003C00u};

    for (int t = 0; t < 32; t++) {
        CPWAIT0();
        __syncthreads();
        if (t + 1 < 32) issueKV(t + 1);

        uint32_t base = s2u(sm + ((t & 1) ? ATN_B1 : ATN_B0));
        uint32_t KS = base, VS = base + 9216;

        // ---- S = Q K^T : one K-fragment load feeds both m-blocks ----
        float sacc[2][8][4];
        #pragma unroll
        for (int mb = 0; mb < 2; mb++)
            #pragma unroll
            for (int i = 0; i < 8; i++)
                #pragma unroll
                for (int k = 0; k < 4; k++) sacc[mb][i][k] = 0.f;

        #pragma unroll
        for (int ks = 0; ks < 4; ks++) {
            #pragma unroll
            for (int nb = 0; nb < 4; nb++) {
                uint32_t bb[4];
                LDSM4(bb[0], bb[1], bb[2], bb[3],
                      KS + (uint32_t)(nb * 16 + lbR) * 144 + ks * 32 + lbK);
                #pragma unroll
                for (int mb = 0; mb < 2; mb++) {
                    mma16816h(sacc[mb][nb * 2],     qf[mb][ks], bb);
                    mma16816h(sacc[mb][nb * 2 + 1], qf[mb][ks], bb + 2);
                }
            }
        }

        // ---- P = exp2(S); O += P V; row sums via ones-MMA (both m-blocks) ----
        #pragma unroll
        for (int ks = 0; ks < 4; ks++) {
            uint32_t ph[2][4];
            #pragma unroll
            for (int mb = 0; mb < 2; mb++) {
                ph[mb][0] = exp2_h2(sacc[mb][2*ks][0],   sacc[mb][2*ks][1]);
                ph[mb][1] = exp2_h2(sacc[mb][2*ks][2],   sacc[mb][2*ks][3]);
                ph[mb][2] = exp2_h2(sacc[mb][2*ks+1][0], sacc[mb][2*ks+1][1]);
                ph[mb][3] = exp2_h2(sacc[mb][2*ks+1][2], sacc[mb][2*ks+1][3]);
                mma16816h(lacc[mb], ph[mb], ones2);
            }
            #pragma unroll
            for (int nb = 0; nb < 4; nb++) {
                uint32_t bb[4];
                LDSM4(bb[0], bb[1], bb[2], bb[3],
                      VS + (uint32_t)(nb * 16 + lbR) * 144 + ks * 32 + lbK);
                #pragma unroll
                for (int mb = 0; mb < 2; mb++) {
                    mma16816h(oacc[mb][nb * 2],     ph[mb], bb);
                    mma16816h(oacc[mb][nb * 2 + 1], ph[mb], bb + 2);
                }
            }
        }
    }

    // ---- finalize: normalize by MMA row sums, write ctx fp16 ----
    const int nn = bh >> 4, hh = bh & 15;
    #pragma unroll
    for (int mb = 0; mb < 2; mb++) {
        float i0 = 1.f / lacc[mb][0], i1 = 1.f / lacc[mb][2];
        const int rA = q0 + w * 32 + mb * 16 + gid, rB = rA + 8;
        #pragma unroll
        for (int nf = 0; nf < 8; nf++) {
            int col = hh * 64 + nf * 8 + qid * 2;
            size_t a1 = ((size_t)nn * SEQ + rA) * EMB + col;
            size_t a2 = ((size_t)nn * SEQ + rB) * EMB + col;
            *(__half2*)&g_Ct[a1] = __floats2half2_rn(oacc[mb][nf][0] * i0, oacc[mb][nf][1] * i0);
            *(__half2*)&g_Ct[a2] = __floats2half2_rn(oacc[mb][nf][2] * i1, oacc[mb][nf][3] * i1);
        }
    }
}

// ---------------------------------------------------------------------------
// fp32 -> fp16 convert of X
// ---------------------------------------------------------------------------
__global__ __launch_bounds__(256) void xhalf_kernel(
    const float* __restrict__ src, __half* __restrict__ dst)
{
    int idx = blockIdx.x * 256 + threadIdx.x;   // float4 index
    float4 v = ((const float4*)src)[idx];
    __half2 h0 = __floats2half2_rn(v.x, v.y);
    __half2 h1 = __floats2half2_rn(v.z, v.w);
    uint2 o; o.x = h2u(h0); o.y = h2u(h1);
    ((uint2*)dst)[idx] = o;
}

// W [k][n] fp32 -> WT [n][k] fp16, 4 weights via blockIdx.z
__global__ __launch_bounds__(256) void whalf_kernel(
    const float* __restrict__ Wq, const float* __restrict__ Wk,
    const float* __restrict__ Wv, const float* __restrict__ Wp)
{
    __shared__ float t[32][33];
    const int z = blockIdx.z;
    const float* W = (z == 0) ? Wq : (z == 1) ? Wk : (z == 2) ? Wv : Wp;
    __half* dst = g_Wt + (size_t)z * EMB * EMB;
    const int n0 = blockIdx.x * 32, k0 = blockIdx.y * 32;
    const int tx = threadIdx.x & 31, ty = threadIdx.x >> 5;

    #pragma unroll
    for (int i = 0; i < 4; i++)
        t[ty + 8 * i][tx] = W[(size_t)(k0 + ty + 8 * i) * EMB + n0 + tx];
    __syncthreads();
    #pragma unroll
    for (int i = 0; i < 4; i++) {
        size_t o = (size_t)(n0 + ty + 8 * i) * EMB + k0 + tx;
        dst[o] = __float2half(t[tx][ty + 8 * i]);
    }
}

// ---------------------------------------------------------------------------
// LayerNorm over last dim (1024). One block per row.
// ---------------------------------------------------------------------------
__global__ __launch_bounds__(256) void ln_kernel(
    const float* __restrict__ gamma, const float* __restrict__ beta,
    float* __restrict__ out)
{
    __shared__ float red[2][8];
    const int r = blockIdx.x;
    const float* x = g_y + (size_t)r * EMB;
    const int tid = threadIdx.x;

    float4 v = *(const float4*)&x[tid * 4];
    float s  = v.x + v.y + v.z + v.w;
    float ss = v.x * v.x + v.y * v.y + v.z * v.z + v.w * v.w;
    #pragma unroll
    for (int off = 16; off >= 1; off >>= 1) {
        s  += __shfl_xor_sync(0xffffffffu, s, off);
        ss += __shfl_xor_sync(0xffffffffu, ss, off);
    }
    int warp = tid >> 5, lane = tid & 31;
    if (lane == 0) { red[0][warp] = s; red[1][warp] = ss; }
    __syncthreads();
    float tot = 0.f, tot2 = 0.f;
    #pragma unroll
    for (int ww = 0; ww < 8; ww++) { tot += red[0][ww]; tot2 += red[1][ww]; }

    const float inv_e = 1.f / (float)EMB;
    float mu  = tot * inv_e;
    float var = tot2 * inv_e - mu * mu;
    float rstd = rsqrtf(var + 1e-8f);

    float4 g = *(const float4*)&gamma[tid * 4];
    float4 b = *(const float4*)&beta[tid * 4];
    float4 o;
    o.x = (v.x - mu) * rstd * g.x + b.x;
    o.y = (v.y - mu) * rstd * g.y + b.y;
    o.z = (v.z - mu) * rstd * g.z + b.z;
    o.w = (v.w - mu) * rstd * g.w + b.w;
    *(float4*)&out[(size_t)r * EMB + tid * 4] = o;
}

// ---------------------------------------------------------------------------
extern "C" void kernel_launch(void* const* d_in, const int* in_sizes, int n_in,
                              void* d_out, int out_size)
{
    const float* X     = (const float*)d_in[0];
    const float* Wq    = (const float*)d_in[1];
    const float* bq    = (const float*)d_in[2];
    const float* Wk    = (const float*)d_in[3];
    const float* bk    = (const float*)d_in[4];
    const float* Wv    = (const float*)d_in[5];
    const float* bv    = (const float*)d_in[6];
    const float* Wp    = (const float*)d_in[7];
    const float* bp    = (const float*)d_in[8];
    const float* gamma = (const float*)d_in[9];
    const float* beta  = (const float*)d_in[10];
    float* out = (float*)d_out;

    cudaFuncSetAttribute(mma_gemm_qkv,
                         cudaFuncAttributeMaxDynamicSharedMemorySize, GEMM_SMEM);
    cudaFuncSetAttribute(mma_gemm_proj,
                         cudaFuncAttributeMaxDynamicSharedMemorySize, GEMM_SMEM);
    cudaFuncSetAttribute(mma_attn,
                         cudaFuncAttributeMaxDynamicSharedMemorySize, ATTN_SMEM);

    __half* xh;
    cudaGetSymbolAddress((void**)&xh, g_Xh);

    // 1. convert input + weights to fp16
    xhalf_kernel<<<MROWS * EMB / 4 / 256, 256>>>(X, xh);
    whalf_kernel<<<dim3(EMB / 32, EMB / 32, 4), 256>>>(Wq, Wk, Wv, Wp);

    // 2. fused QKV projections (R13 double-buffer mainloop, 3 CTAs/SM)
    mma_gemm_qkv<<<dim3(EMB / 128, MROWS / 128, 3), 128, GEMM_SMEM>>>(bq, bk, bv);

    // 3. attention (4 warps x 32 rows, shared K/V fragments)
    mma_attn<<<dim3(NB * NH, SEQ / 128), 128, ATTN_SMEM>>>();

    // 4. output projection (+bias+residual)
    mma_gemm_proj<<<dim3(EMB / 128, MROWS / 128), 128, GEMM_SMEM>>>(X, bp);

    // 5. layernorm
    ln_kernel<<<MROWS, 256>>>(gamma, beta, out);
}

// round 17
// speedup vs baseline: 1.0382x; 1.0382x over previous
#include <cuda_runtime.h>
#include <cuda_bf16.h>
#include <cuda_fp16.h>
#include <cstdint>

// Problem constants
#define NB   4
#define SEQ  2048
#define EMB  1024
#define NH   16
#define HD   64
#define MROWS (NB*SEQ)   // 8192

// ---------------------------------------------------------------------------
// Scratch (static device arrays) — all-fp16 pipeline
// ---------------------------------------------------------------------------
__device__ __half g_Xh[MROWS*EMB];          // input fp16
__device__ __half g_Ct[MROWS*EMB];          // ctx fp16 [n,l,e]
__device__ __half g_Qs[MROWS*EMB];          // [n,h,l,d], scaled by log2e/8
__device__ __half g_Kf[MROWS*EMB];          // [n,h,l,d]
__device__ __half g_Vt[MROWS*EMB];          // [n,h,d,l]
__device__ __half g_Wt[4*(size_t)EMB*EMB];  // transposed [n][k] x4 (q,k,v,p)
__device__ float g_y[MROWS*EMB];

// ---------------------------------------------------------------------------
// PTX helpers (arch-neutral sm_80-era instructions)
// ---------------------------------------------------------------------------
__device__ __forceinline__ uint32_t s2u(const void* p) {
    return (uint32_t)__cvta_generic_to_shared(p);
}
#define CP16(d, s) asm volatile("cp.async.cg.shared.global [%0], [%1], 16;" :: "r"(d), "l"(s))
#define CPCOMMIT() asm volatile("cp.async.commit_group;")
#define CPWAIT0()  asm volatile("cp.async.wait_group 0;")
#define CPWAIT1()  asm volatile("cp.async.wait_group 1;")
#define LDSM4(r0,r1,r2,r3,a) \
    asm volatile("ldmatrix.sync.aligned.m8n8.x4.shared.b16 {%0,%1,%2,%3}, [%4];" \
        : "=r"(r0),"=r"(r1),"=r"(r2),"=r"(r3) : "r"(a))

__device__ __forceinline__ void mma16816h(float* c, const uint32_t* a, const uint32_t* b) {
    asm volatile(
        "mma.sync.aligned.m16n8k16.row.col.f32.f16.f16.f32 "
        "{%0,%1,%2,%3}, {%4,%5,%6,%7}, {%8,%9}, {%0,%1,%2,%3};"
        : "+f"(c[0]), "+f"(c[1]), "+f"(c[2]), "+f"(c[3])
        : "r"(a[0]), "r"(a[1]), "r"(a[2]), "r"(a[3]), "r"(b[0]), "r"(b[1]));
}

__device__ __forceinline__ uint32_t h2u(__half2 h) {
    return *reinterpret_cast<uint32_t*>(&h);
}

// pack two fp32 to half2 then exp2 both (one MUFU f16x2 op)
__device__ __forceinline__ uint32_t exp2_h2(float a, float b) {
    uint32_t s = h2u(__floats2half2_rn(a, b));
    uint32_t d;
    asm("ex2.approx.f16x2 %0, %1;" : "=r"(d) : "r"(s));
    return d;
}

// ---------------------------------------------------------------------------
// Single-fp16 GEMM mainloop (R13 exact): CTA 128x128, 128 threads
// (4 warps, 2m x 2n), warp tile 64x64, double-buffered cp.async with
// compile-time (i&1) buffer selection, natural register allocation.
// ---------------------------------------------------------------------------
#define GBUF 36864
#define GEMM_SMEM (2*GBUF)   // 73728; epilogue Ds (128*132*4=67584) aliases 0

__device__ __forceinline__ void gemm_core(
    char* sm,
    const __half* __restrict__ A, const __half* __restrict__ B,
    int m0, int n0, float acc[4][8][4])
{
    const int tid = threadIdx.x, lane = tid & 31, w = tid >> 5;  // 4 warps
    const int wm = w >> 1, wn = w & 1;

    auto issue = [&](int chunk) {
        int kk = chunk * 64;
        uint32_t base = s2u(sm + (chunk & 1) * GBUF);
        #pragma unroll
        for (int j = 0; j < 8; j++) {
            int idx = tid + j * 128, row = idx >> 3, c = (idx & 7) * 8;
            uint32_t so = row * 144 + c * 2;
            CP16(base + so,         A + (size_t)(m0 + row) * EMB + kk + c);
            CP16(base + 18432 + so, B + (size_t)(n0 + row) * EMB + kk + c);
        }
        CPCOMMIT();
    };

    issue(0); issue(1);

    const int laR = lane & 15, laK = (lane >> 4) * 16;
    const int lbR = (lane & 7) + ((lane >> 4) & 1) * 8, lbK = ((lane >> 3) & 1) * 16;

    for (int i = 0; i < 16; i++) {
        if (i >= 14) { CPWAIT0(); } else { CPWAIT1(); }
        __syncthreads();
        uint32_t b0 = s2u(sm + (i & 1) * GBUF);
        uint32_t aS = b0, bS = b0 + 18432;
        #pragma unroll
        for (int ks = 0; ks < 4; ks++) {
            uint32_t a[4][4], b[8][2];
            #pragma unroll
            for (int ma = 0; ma < 4; ma++)
                LDSM4(a[ma][0], a[ma][1], a[ma][2], a[ma][3],
                      aS + (uint32_t)(wm * 64 + ma * 16 + laR) * 144 + ks * 32 + laK);
            #pragma unroll
            for (int nb = 0; nb < 4; nb++)
                LDSM4(b[nb*2][0], b[nb*2][1], b[nb*2+1][0], b[nb*2+1][1],
                      bS + (uint32_t)(wn * 64 + nb * 16 + lbR) * 144 + ks * 32 + lbK);
            #pragma unroll
            for (int ma = 0; ma < 4; ma++)
                #pragma unroll
                for (int na = 0; na < 8; na++)
                    mma16816h(acc[ma][na], a[ma], b[na]);
        }
        __syncthreads();
        if (i + 2 < 16) issue(i + 2);
    }
}

__device__ __forceinline__ void stage_acc(char* sm, float acc[4][8][4])
{
    float* Ds = (float*)sm;
    const int lane = threadIdx.x & 31, w = threadIdx.x >> 5;
    const int wm = w >> 1, wn = w & 1;
    const int gid = lane >> 2, qid = lane & 3;
    #pragma unroll
    for (int ma = 0; ma < 4; ma++)
        #pragma unroll
        for (int na = 0; na < 8; na++) {
            int m = wm * 64 + ma * 16 + gid, n = wn * 64 + na * 8 + qid * 2;
            float* c = acc[ma][na];
            *(float2*)&Ds[m * 132 + n]       = make_float2(c[0], c[1]);
            *(float2*)&Ds[(m + 8) * 132 + n] = make_float2(c[2], c[3]);
        }
    __syncthreads();
}

// ---------------------------------------------------------------------------
// Fused QKV projection: blockIdx.z = 0(Q) / 1(K) / 2(V). 128 threads.
// ---------------------------------------------------------------------------
__global__ __launch_bounds__(128) void mma_gemm_qkv(
    const float* __restrict__ bq, const float* __restrict__ bk,
    const float* __restrict__ bv)
{
    extern __shared__ char sm[];
    const int tid = threadIdx.x, lane = tid & 31, w = tid >> 5;
    const int m0 = blockIdx.y * 128, n0 = blockIdx.x * 128;
    const int mode = blockIdx.z;
    const float* bias = (mode == 0) ? bq : (mode == 1) ? bk : bv;

    float acc[4][8][4];
    #pragma unroll
    for (int i = 0; i < 4; i++)
        #pragma unroll
        for (int j = 0; j < 8; j++)
            #pragma unroll
            for (int k = 0; k < 4; k++) acc[i][j][k] = 0.f;

    gemm_core(sm, g_Xh, g_Wt + (size_t)mode * EMB * EMB, m0, n0, acc);
    stage_acc(sm, acc);
    float* Ds = (float*)sm;

    if (mode <= 1) {
        __half* O = (mode == 0) ? g_Qs : g_Kf;
        const float scale = (mode == 0) ? 0.125f * 1.44269504089f : 1.0f;
        #pragma unroll
        for (int it = 0; it < 32; it++) {
            int t = tid + it * 128, row = t >> 5, g = t & 31;
            int c = n0 + g * 4, r = m0 + row;
            float4 v  = *(float4*)&Ds[row * 132 + g * 4];
            float4 bi = *(const float4*)&bias[c];
            v.x = (v.x + bi.x) * scale; v.y = (v.y + bi.y) * scale;
            v.z = (v.z + bi.z) * scale; v.w = (v.w + bi.w) * scale;
            int nn = r >> 11, l = r & 2047, hh = c >> 6, dd = c & 63;
            size_t o = (((size_t)(nn * NH + hh) * SEQ) + l) * HD + dd;
            uint2 pk;
            pk.x = h2u(__floats2half2_rn(v.x, v.y));
            pk.y = h2u(__floats2half2_rn(v.z, v.w));
            *(uint2*)&O[o] = pk;          // one 8B store (o is 4-half aligned)
        }
    } else {
        // V transposed -> [n,h,d,l], fp16
        const int nn = m0 >> 11, lb = m0 & 2047;
        #pragma unroll
        for (int cc = 0; cc < 32; cc++) {
            int c = n0 + w * 32 + cc;
            float bi = bias[c];
            int hh = c >> 6, dd = c & 63;
            size_t ob = ((size_t)(nn * NH + hh) * HD + dd) * SEQ + lb;
            #pragma unroll
            for (int mi = 0; mi < 4; mi++) {
                int m = mi * 32 + lane;
                g_Vt[ob + m] = __float2half(Ds[m * 132 + (c - n0)] + bi);
            }
        }
    }
}

// ---------------------------------------------------------------------------
// Output projection: ctx(fp16) @ Wp + bp + residual -> g_y (fp32). 128 threads.
// ---------------------------------------------------------------------------
__global__ __launch_bounds__(128) void mma_gemm_proj(
    const float* __restrict__ resid, const float* __restrict__ bias)
{
    extern __shared__ char sm[];
    const int tid = threadIdx.x;
    const int m0 = blockIdx.y * 128, n0 = blockIdx.x * 128;

    float acc[4][8][4];
    #pragma unroll
    for (int i = 0; i < 4; i++)
        #pragma unroll
        for (int j = 0; j < 8; j++)
            #pragma unroll
            for (int k = 0; k < 4; k++) acc[i][j][k] = 0.f;

    gemm_core(sm, g_Ct, g_Wt + 3 * (size_t)EMB * EMB, m0, n0, acc);
    stage_acc(sm, acc);
    float* Ds = (float*)sm;

    #pragma unroll
    for (int it = 0; it < 32; it++) {
        int t = tid + it * 128, row = t >> 5, g = t & 31;
        int c = n0 + g * 4, r = m0 + row;
        float4 v  = *(float4*)&Ds[row * 132 + g * 4];
        float4 bi = *(const float4*)&bias[c];
        float4 rv = *(const float4*)&resid[(size_t)r * EMB + c];
        v.x += bi.x + rv.x; v.y += bi.y + rv.y;
        v.z += bi.z + rv.z; v.w += bi.w + rv.w;
        *(float4*)&g_y[(size_t)r * EMB + c] = v;
    }
}

// ---------------------------------------------------------------------------
// Flash attention (R13 exact): 128 threads, 4 warps x 32 query rows,
// shared K/V fragments, max-free softmax, ex2.approx.f16x2, ones-MMA sums.
// smem: 2 x [K (64x144=9216) | V (9216)] = 36864 B.
// ---------------------------------------------------------------------------
#define ATN_B0  0
#define ATN_B1  18432
#define ATTN_SMEM 36864

__global__ __launch_bounds__(128) void mma_attn()
{
    extern __shared__ char sm[];
    const int tid = threadIdx.x, lane = tid & 31, w = tid >> 5;  // 4 warps
    const int gid = lane >> 2, qid = lane & 3;
    const int bh = blockIdx.x, q0 = blockIdx.y * 128;

    const __half* Qp = g_Qs + ((size_t)bh * SEQ + q0) * HD;
    const __half* Kp = g_Kf + (size_t)bh * SEQ * HD;
    const __half* Vp = g_Vt + (size_t)bh * HD * SEQ;

    const int laR = lane & 15, laK = (lane >> 4) * 16;
    const int lbR = (lane & 7) + ((lane >> 4) & 1) * 8, lbK = ((lane >> 3) & 1) * 16;

    // ---- pre-loop: stage Q (128x144) into B1 area ----
    {
        uint32_t st = s2u(sm + ATN_B1);
        #pragma unroll
        for (int j = 0; j < 8; j++) {
            int idx = tid + j * 128, row = idx >> 3, c = (idx & 7) * 8;
            CP16(st + row * 144 + c * 2, Qp + (size_t)row * HD + c);
        }
        CPCOMMIT();
    }

    auto issueKV = [&](int t) {
        uint32_t base = s2u(sm + ((t & 1) ? ATN_B1 : ATN_B0));
        #pragma unroll
        for (int j = 0; j < 8; j++) {
            int idx = tid + j * 128;
            int which = idx >> 9, rem = idx & 511, row = rem >> 3, c = (rem & 7) * 8;
            uint32_t dst = base + which * 9216 + row * 144 + c * 2;
            if (which == 0) CP16(dst, Kp + (size_t)(t * 64 + row) * HD + c);
            else            CP16(dst, Vp + (size_t)row * SEQ + t * 64 + c);
        }
        CPCOMMIT();
    };

    issueKV(0);
    CPWAIT1();          // Q staging done (KV(0) may still be pending)
    __syncthreads();

    // extract Q fragments for both 16-row m-blocks (registers, all 32 tiles)
    uint32_t qf[2][4][4];
    {
        uint32_t st = s2u(sm + ATN_B1);
        #pragma unroll
        for (int mb = 0; mb < 2; mb++)
            #pragma unroll
            for (int ks = 0; ks < 4; ks++)
                LDSM4(qf[mb][ks][0], qf[mb][ks][1], qf[mb][ks][2], qf[mb][ks][3],
                      st + (uint32_t)(w * 32 + mb * 16 + laR) * 144 + ks * 32 + laK);
    }
    __syncthreads();    // B1 free for KV(1)

    float oacc[2][8][4];
    #pragma unroll
    for (int mb = 0; mb < 2; mb++)
        #pragma unroll
        for (int i = 0; i < 8; i++)
            #pragma unroll
            for (int k = 0; k < 4; k++) oacc[mb][i][k] = 0.f;
    float lacc[2][4] = {{0.f,0.f,0.f,0.f},{0.f,0.f,0.f,0.f}};
    const uint32_t ones2[2] = {0x3C003C00u, 0x3C003C00u};

    for (int t = 0; t < 32; t++) {
        CPWAIT0();
        __syncthreads();
        if (t + 1 < 32) issueKV(t + 1);

        uint32_t base = s2u(sm + ((t & 1) ? ATN_B1 : ATN_B0));
        uint32_t KS = base, VS = base + 9216;

        // ---- S = Q K^T : one K-fragment load feeds both m-blocks ----
        float sacc[2][8][4];
        #pragma unroll
        for (int mb = 0; mb < 2; mb++)
            #pragma unroll
            for (int i = 0; i < 8; i++)
                #pragma unroll
                for (int k = 0; k < 4; k++) sacc[mb][i][k] = 0.f;

        #pragma unroll
        for (int ks = 0; ks < 4; ks++) {
            #pragma unroll
            for (int nb = 0; nb < 4; nb++) {
                uint32_t bb[4];
                LDSM4(bb[0], bb[1], bb[2], bb[3],
                      KS + (uint32_t)(nb * 16 + lbR) * 144 + ks * 32 + lbK);
                #pragma unroll
                for (int mb = 0; mb < 2; mb++) {
                    mma16816h(sacc[mb][nb * 2],     qf[mb][ks], bb);
                    mma16816h(sacc[mb][nb * 2 + 1], qf[mb][ks], bb + 2);
                }
            }
        }

        // ---- P = exp2(S); O += P V; row sums via ones-MMA (both m-blocks) ----
        #pragma unroll
        for (int ks = 0; ks < 4; ks++) {
            uint32_t ph[2][4];
            #pragma unroll
            for (int mb = 0; mb < 2; mb++) {
                ph[mb][0] = exp2_h2(sacc[mb][2*ks][0],   sacc[mb][2*ks][1]);
                ph[mb][1] = exp2_h2(sacc[mb][2*ks][2],   sacc[mb][2*ks][3]);
                ph[mb][2] = exp2_h2(sacc[mb][2*ks+1][0], sacc[mb][2*ks+1][1]);
                ph[mb][3] = exp2_h2(sacc[mb][2*ks+1][2], sacc[mb][2*ks+1][3]);
                mma16816h(lacc[mb], ph[mb], ones2);
            }
            #pragma unroll
            for (int nb = 0; nb < 4; nb++) {
                uint32_t bb[4];
                LDSM4(bb[0], bb[1], bb[2], bb[3],
                      VS + (uint32_t)(nb * 16 + lbR) * 144 + ks * 32 + lbK);
                #pragma unroll
                for (int mb = 0; mb < 2; mb++) {
                    mma16816h(oacc[mb][nb * 2],     ph[mb], bb);
                    mma16816h(oacc[mb][nb * 2 + 1], ph[mb], bb + 2);
                }
            }
        }
    }

    // ---- finalize: normalize by MMA row sums, write ctx fp16 ----
    const int nn = bh >> 4, hh = bh & 15;
    #pragma unroll
    for (int mb = 0; mb < 2; mb++) {
        float i0 = 1.f / lacc[mb][0], i1 = 1.f / lacc[mb][2];
        const int rA = q0 + w * 32 + mb * 16 + gid, rB = rA + 8;
        #pragma unroll
        for (int nf = 0; nf < 8; nf++) {
            int col = hh * 64 + nf * 8 + qid * 2;
            size_t a1 = ((size_t)nn * SEQ + rA) * EMB + col;
            size_t a2 = ((size_t)nn * SEQ + rB) * EMB + col;
            *(__half2*)&g_Ct[a1] = __floats2half2_rn(oacc[mb][nf][0] * i0, oacc[mb][nf][1] * i0);
            *(__half2*)&g_Ct[a2] = __floats2half2_rn(oacc[mb][nf][2] * i1, oacc[mb][nf][3] * i1);
        }
    }
}

// ---------------------------------------------------------------------------
// fp32 -> fp16 convert of X
// ---------------------------------------------------------------------------
__global__ __launch_bounds__(256) void xhalf_kernel(
    const float* __restrict__ src, __half* __restrict__ dst)
{
    int idx = blockIdx.x * 256 + threadIdx.x;   // float4 index
    float4 v = ((const float4*)src)[idx];
    __half2 h0 = __floats2half2_rn(v.x, v.y);
    __half2 h1 = __floats2half2_rn(v.z, v.w);
    uint2 o; o.x = h2u(h0); o.y = h2u(h1);
    ((uint2*)dst)[idx] = o;
}

// W [k][n] fp32 -> WT [n][k] fp16, 4 weights via blockIdx.z
__global__ __launch_bounds__(256) void whalf_kernel(
    const float* __restrict__ Wq, const float* __restrict__ Wk,
    const float* __restrict__ Wv, const float* __restrict__ Wp)
{
    __shared__ float t[32][33];
    const int z = blockIdx.z;
    const float* W = (z == 0) ? Wq : (z == 1) ? Wk : (z == 2) ? Wv : Wp;
    __half* dst = g_Wt + (size_t)z * EMB * EMB;
    const int n0 = blockIdx.x * 32, k0 = blockIdx.y * 32;
    const int tx = threadIdx.x & 31, ty = threadIdx.x >> 5;

    #pragma unroll
    for (int i = 0; i < 4; i++)
        t[ty + 8 * i][tx] = W[(size_t)(k0 + ty + 8 * i) * EMB + n0 + tx];
    __syncthreads();
    #pragma unroll
    for (int i = 0; i < 4; i++) {
        size_t o = (size_t)(n0 + ty + 8 * i) * EMB + k0 + tx;
        dst[o] = __float2half(t[tx][ty + 8 * i]);
    }
}

// ---------------------------------------------------------------------------
// LayerNorm over last dim (1024). One block per row.
// ---------------------------------------------------------------------------
__global__ __launch_bounds__(256) void ln_kernel(
    const float* __restrict__ gamma, const float* __restrict__ beta,
    float* __restrict__ out)
{
    __shared__ float red[2][8];
    const int r = blockIdx.x;
    const float* x = g_y + (size_t)r * EMB;
    const int tid = threadIdx.x;

    float4 v = *(const float4*)&x[tid * 4];
    float s  = v.x + v.y + v.z + v.w;
    float ss = v.x * v.x + v.y * v.y + v.z * v.z + v.w * v.w;
    #pragma unroll
    for (int off = 16; off >= 1; off >>= 1) {
        s  += __shfl_xor_sync(0xffffffffu, s, off);
        ss += __shfl_xor_sync(0xffffffffu, ss, off);
    }
    int warp = tid >> 5, lane = tid & 31;
    if (lane == 0) { red[0][warp] = s; red[1][warp] = ss; }
    __syncthreads();
    float tot = 0.f, tot2 = 0.f;
    #pragma unroll
    for (int ww = 0; ww < 8; ww++) { tot += red[0][ww]; tot2 += red[1][ww]; }

    const float inv_e = 1.f / (float)EMB;
    float mu  = tot * inv_e;
    float var = tot2 * inv_e - mu * mu;
    float rstd = rsqrtf(var + 1e-8f);

    float4 g = *(const float4*)&gamma[tid * 4];
    float4 b = *(const float4*)&beta[tid * 4];
    float4 o;
    o.x = (v.x - mu) * rstd * g.x + b.x;
    o.y = (v.y - mu) * rstd * g.y + b.y;
    o.z = (v.z - mu) * rstd * g.z + b.z;
    o.w = (v.w - mu) * rstd * g.w + b.w;
    *(float4*)&out[(size_t)r * EMB + tid * 4] = o;
}

// ---------------------------------------------------------------------------
extern "C" void kernel_launch(void* const* d_in, const int* in_sizes, int n_in,
                              void* d_out, int out_size)
{
    const float* X     = (const float*)d_in[0];
    const float* Wq    = (const float*)d_in[1];
    const float* bq    = (const float*)d_in[2];
    const float* Wk    = (const float*)d_in[3];
    const float* bk    = (const float*)d_in[4];
    const float* Wv    = (const float*)d_in[5];
    const float* bv    = (const float*)d_in[6];
    const float* Wp    = (const float*)d_in[7];
    const float* bp    = (const float*)d_in[8];
    const float* gamma = (const float*)d_in[9];
    const float* beta  = (const float*)d_in[10];
    float* out = (float*)d_out;

    cudaFuncSetAttribute(mma_gemm_qkv,
                         cudaFuncAttributeMaxDynamicSharedMemorySize, GEMM_SMEM);
    cudaFuncSetAttribute(mma_gemm_proj,
                         cudaFuncAttributeMaxDynamicSharedMemorySize, GEMM_SMEM);
    cudaFuncSetAttribute(mma_attn,
                         cudaFuncAttributeMaxDynamicSharedMemorySize, ATTN_SMEM);

    __half* xh;
    cudaGetSymbolAddress((void**)&xh, g_Xh);

    // 1. convert input + weights to fp16
    xhalf_kernel<<<MROWS * EMB / 4 / 256, 256>>>(X, xh);
    whalf_kernel<<<dim3(EMB / 32, EMB / 32, 4), 256>>>(Wq, Wk, Wv, Wp);

    // 2. fused QKV projections (R13 double-buffer mainloop)
    mma_gemm_qkv<<<dim3(EMB / 128, MROWS / 128, 3), 128, GEMM_SMEM>>>(bq, bk, bv);

    // 3. attention (4 warps x 32 rows, shared K/V fragments)
    mma_attn<<<dim3(NB * NH, SEQ / 128), 128, ATTN_SMEM>>>();

    // 4. output projection (+bias+residual)
    mma_gemm_proj<<<dim3(EMB / 128, MROWS / 128), 128, GEMM_SMEM>>>(X, bp);

    // 5. layernorm
    ln_kernel<<<MROWS, 256>>>(gamma, beta, out);
}